// round 2
// baseline (speedup 1.0000x reference)
#include <cuda_runtime.h>
#include <stdint.h>

#define Cc 1000
#define Bb 16384
#define C4 250   // Cc / 4
#define WPB 8    // warps per block

// 4 MB scratch for transposed T (column y of T becomes contiguous row y of Tt)
__device__ float d_Tt[Cc * Cc];
__device__ int   d_is64;   // 1 if target buffer is int64, 0 if int32

__global__ void zero_out_kernel(float* o) { *o = 0.0f; }

// Detect target dtype: for little-endian int64 values < 1000, every odd
// 32-bit word is zero. For int32 labels, odd words are random labels
// (all-zero prob ~1e-24 over 16 probes).
__global__ void detect_kernel(const int* __restrict__ t32) {
    int acc = 0;
    #pragma unroll
    for (int i = 1; i < 32; i += 2) acc |= t32[i];
    d_is64 = (acc == 0) ? 1 : 0;
}

// Tiled transpose: Tt[a*Cc + b] = T[b*Cc + a]
__global__ void transpose_kernel(const float* __restrict__ T) {
    __shared__ float tile[32][33];
    int x = blockIdx.x * 32 + threadIdx.x;
    int y = blockIdx.y * 32 + threadIdx.y;
    if (x < Cc && y < Cc) tile[threadIdx.y][threadIdx.x] = T[y * Cc + x];
    __syncthreads();
    x = blockIdx.y * 32 + threadIdx.x;
    y = blockIdx.x * 32 + threadIdx.y;
    if (x < Cc && y < Cc) d_Tt[y * Cc + x] = tile[threadIdx.x][threadIdx.y];
}

// One warp per row. Single pass: S = sum exp(o), D = sum exp(o)*Tt[y][c], o_y.
// contrib = (exp(o_y)/D) * (log(S) - o_y); block-reduce then one atomicAdd.
__global__ void __launch_bounds__(WPB * 32)
reweight_kernel(const float* __restrict__ out,
                const void* __restrict__ target,
                float* __restrict__ result) {
    const int warp = threadIdx.x >> 5;
    const int lane = threadIdx.x & 31;
    const int row  = blockIdx.x * WPB + warp;

    float contrib = 0.0f;
    {
        int y;
        if (d_is64) y = (int)((const long long*)target)[row];
        else        y = ((const int*)target)[row];
        y = min(max(y, 0), Cc - 1);   // guard against OOB if detection ever wrong

        const float4* o4 = (const float4*)(out + (size_t)row * Cc);
        const float4* t4 = (const float4*)(d_Tt + (size_t)y * Cc);
        const int yj = y >> 2, yk = y & 3;

        float s = 0.0f, d = 0.0f, oy = 0.0f;
        #pragma unroll 4
        for (int j = lane; j < C4; j += 32) {
            float4 v = o4[j];
            float4 t = t4[j];
            float e0 = __expf(v.x), e1 = __expf(v.y);
            float e2 = __expf(v.z), e3 = __expf(v.w);
            s += (e0 + e1) + (e2 + e3);
            d += (e0 * t.x + e1 * t.y) + (e2 * t.z + e3 * t.w);
            if (j == yj) oy = (yk == 0) ? v.x : (yk == 1) ? v.y : (yk == 2) ? v.z : v.w;
        }
        #pragma unroll
        for (int off = 16; off; off >>= 1) {
            s  += __shfl_xor_sync(0xffffffff, s,  off);
            d  += __shfl_xor_sync(0xffffffff, d,  off);
            oy += __shfl_xor_sync(0xffffffff, oy, off);  // only one lane nonzero
        }
        if (lane == 0) {
            float beta = __expf(oy) / d;     // softmax denom cancels in pro1/pro2
            float ce   = __logf(s) - oy;     // -log_softmax[y]
            contrib = beta * ce;
        }
    }

    __shared__ float part[WPB];
    if (lane == 0) part[warp] = contrib;
    __syncthreads();
    if (threadIdx.x == 0) {
        float t = 0.0f;
        #pragma unroll
        for (int w = 0; w < WPB; w++) t += part[w];
        atomicAdd(result, t);
    }
}

extern "C" void kernel_launch(void* const* d_in, const int* in_sizes, int n_in,
                              void* d_out, int out_size) {
    const float* out    = (const float*)d_in[0];
    const void*  target = d_in[1];
    const float* T      = (const float*)d_in[2];
    float* res = (float*)d_out;

    zero_out_kernel<<<1, 1>>>(res);
    detect_kernel<<<1, 1>>>((const int*)target);

    dim3 tb(32, 32);
    dim3 tg((Cc + 31) / 32, (Cc + 31) / 32);
    transpose_kernel<<<tg, tb>>>(T);

    reweight_kernel<<<Bb / WPB, WPB * 32>>>(out, target, res);
}

// round 3
// speedup vs baseline: 1.0015x; 1.0015x over previous
#include <cuda_runtime.h>
#include <cuda_pipeline.h>
#include <stdint.h>

#define Cc 1000
#define Bb 16384
#define C4 250            // Cc / 4
#define WPB 6             // warps per block (6*8000B = 48000B static smem <= 48KB)
#define NBLK ((Bb + WPB - 1) / WPB)

__device__ float d_Tt[Cc * Cc];
__device__ int   d_is64;

// Fused prep: transpose T -> d_Tt, zero the result, detect target dtype.
__global__ void prep_kernel(const float* __restrict__ T,
                            const int* __restrict__ t32,
                            float* __restrict__ res) {
    if (blockIdx.x == 0 && blockIdx.y == 0 && threadIdx.y == 0) {
        if (threadIdx.x == 0) *res = 0.0f;
        if (threadIdx.x == 1) {
            // int64 labels < 1000: every odd 32-bit word is 0. int32 labels:
            // odd words are random labels (all-zero prob ~1e-24 over 16 probes).
            int acc = 0;
            #pragma unroll
            for (int i = 1; i < 32; i += 2) acc |= t32[i];
            d_is64 = (acc == 0) ? 1 : 0;
        }
    }
    __shared__ float tile[32][33];
    int x = blockIdx.x * 32 + threadIdx.x;
    int y = blockIdx.y * 32 + threadIdx.y;
    if (x < Cc && y < Cc) tile[threadIdx.y][threadIdx.x] = T[y * Cc + x];
    __syncthreads();
    x = blockIdx.y * 32 + threadIdx.x;
    y = blockIdx.x * 32 + threadIdx.y;
    if (x < Cc && y < Cc) d_Tt[y * Cc + x] = tile[threadIdx.x][threadIdx.y];
}

// One warp per row. cp.async-stage the out row AND the Tt row into SMEM
// (in-flight bytes live in SMEM, not registers), then compute from LDS.
// contrib = (exp(o_y)/D) * (log(S) - o_y), summed via one atomic per block.
__global__ void __launch_bounds__(WPB * 32)
reweight_kernel(const float* __restrict__ out,
                const void* __restrict__ target,
                float* __restrict__ result) {
    __shared__ __align__(16) float sm[WPB * 2000];  // per warp: 1000 out + 1000 Tt
    const int warp = threadIdx.x >> 5;
    const int lane = threadIdx.x & 31;
    const int row  = blockIdx.x * WPB + warp;

    float contrib = 0.0f;
    if (row < Bb) {
        int y;
        if (d_is64) y = (int)((const long long*)target)[row];
        else        y = ((const int*)target)[row];
        y = min(max(y, 0), Cc - 1);

        float* smo = sm + warp * 2000;
        float* smt = smo + 1000;
        const float4* o4 = (const float4*)(out + (size_t)row * Cc);
        const float4* t4 = (const float4*)(d_Tt + (size_t)y * Cc);

        // Stage both rows: 2 * 250 x 16B cp.async per warp, fire-and-forget.
        #pragma unroll
        for (int i = 0; i < 8; i++) {
            int j = lane + 32 * i;
            if (j < C4) {
                __pipeline_memcpy_async((float4*)smo + j, o4 + j, 16);
                __pipeline_memcpy_async((float4*)smt + j, t4 + j, 16);
            }
        }
        __pipeline_commit();
        __pipeline_wait_prior(0);
        __syncwarp();

        float s = 0.0f, dsum = 0.0f;
        #pragma unroll
        for (int i = 0; i < 8; i++) {
            int j = lane + 32 * i;
            if (j < C4) {
                float4 v = ((const float4*)smo)[j];
                float4 t = ((const float4*)smt)[j];
                float e0 = __expf(v.x), e1 = __expf(v.y);
                float e2 = __expf(v.z), e3 = __expf(v.w);
                s    += (e0 + e1) + (e2 + e3);
                dsum += (e0 * t.x + e1 * t.y) + (e2 * t.z + e3 * t.w);
            }
        }
        #pragma unroll
        for (int off = 16; off; off >>= 1) {
            s    += __shfl_xor_sync(0xffffffff, s,    off);
            dsum += __shfl_xor_sync(0xffffffff, dsum, off);
        }
        if (lane == 0) {
            float oy = smo[y];                  // target logit, already staged
            float beta = __expf(oy) / dsum;     // softmax denom cancels
            contrib = beta * (__logf(s) - oy);  // beta * (-log_softmax[y])
        }
    }

    __shared__ float part[WPB];
    if (lane == 0) part[warp] = contrib;
    __syncthreads();
    if (threadIdx.x == 0) {
        float t = 0.0f;
        #pragma unroll
        for (int w = 0; w < WPB; w++) t += part[w];
        atomicAdd(result, t);
    }
}

extern "C" void kernel_launch(void* const* d_in, const int* in_sizes, int n_in,
                              void* d_out, int out_size) {
    const float* out    = (const float*)d_in[0];
    const void*  target = d_in[1];
    const float* T      = (const float*)d_in[2];
    float* res = (float*)d_out;

    dim3 tb(32, 32);
    dim3 tg((Cc + 31) / 32, (Cc + 31) / 32);
    prep_kernel<<<tg, tb>>>(T, (const int*)target, res);

    reweight_kernel<<<NBLK, WPB * 32>>>(out, target, res);
}

// round 4
// speedup vs baseline: 1.1044x; 1.1027x over previous
#include <cuda_runtime.h>
#include <stdint.h>

#define Cc 1000
#define Bb 16384
#define C4 250            // Cc / 4
#define ROW_BYTES 4000    // Cc * 4, multiple of 16
#define WPB 6             // warps per block; 6*8000B staged = 48000B smem
#define NBLK ((Bb + WPB - 1) / WPB)

__device__ float d_Tt[Cc * Cc];
__device__ int   d_is64;

__device__ __forceinline__ uint32_t smem_u32(const void* p) {
    uint32_t a;
    asm("{ .reg .u64 t; cvta.to.shared.u64 t, %1; cvt.u32.u64 %0, t; }"
        : "=r"(a) : "l"(p));
    return a;
}

// Fused prep: transpose T -> d_Tt, zero result, detect target dtype.
__global__ void prep_kernel(const float* __restrict__ T,
                            const int* __restrict__ t32,
                            float* __restrict__ res) {
    if (blockIdx.x == 0 && blockIdx.y == 0 && threadIdx.y == 0) {
        if (threadIdx.x == 0) *res = 0.0f;
        if (threadIdx.x == 1) {
            // int64 labels < 1000: every odd 32-bit word is 0; int32 labels:
            // odd words are random labels (false-positive prob ~1e-24).
            int acc = 0;
            #pragma unroll
            for (int i = 1; i < 32; i += 2) acc |= t32[i];
            d_is64 = (acc == 0) ? 1 : 0;
        }
    }
    __shared__ float tile[32][33];
    int x = blockIdx.x * 32 + threadIdx.x;
    int y = blockIdx.y * 32 + threadIdx.y;
    if (x < Cc && y < Cc) tile[threadIdx.y][threadIdx.x] = T[y * Cc + x];
    __syncthreads();
    x = blockIdx.y * 32 + threadIdx.x;
    y = blockIdx.x * 32 + threadIdx.y;
    if (x < Cc && y < Cc) d_Tt[y * Cc + x] = tile[threadIdx.x][threadIdx.y];
}

// One warp per row. Two cp.async.bulk (4000B each) stage the out row and the
// Tt[y] row into smem; mbarrier complete_tx signals arrival. Compute from LDS.
__global__ void __launch_bounds__(WPB * 32)
reweight_kernel(const float* __restrict__ out,
                const void* __restrict__ target,
                float* __restrict__ result) {
    __shared__ __align__(16) float sm[WPB * 2000];  // per warp: 1000 out + 1000 Tt
    __shared__ __align__(8) unsigned long long mbar[WPB];
    __shared__ float part[WPB];

    const int warp = threadIdx.x >> 5;
    const int lane = threadIdx.x & 31;
    const int row  = blockIdx.x * WPB + warp;

    // Init all per-warp mbarriers once, make them visible to the async proxy.
    if (threadIdx.x < WPB) {
        uint32_t mb = smem_u32(&mbar[threadIdx.x]);
        asm volatile("mbarrier.init.shared.b64 [%0], 1;" :: "r"(mb) : "memory");
    }
    __syncthreads();
    asm volatile("fence.proxy.async.shared::cta;" ::: "memory");

    float contrib = 0.0f;
    if (row < Bb) {
        int y;
        if (d_is64) y = (int)((const long long*)target)[row];
        else        y = ((const int*)target)[row];
        y = min(max(y, 0), Cc - 1);

        float* smo = sm + warp * 2000;
        float* smt = smo + 1000;
        uint32_t mb = smem_u32(&mbar[warp]);

        if (lane == 0) {
            asm volatile("mbarrier.arrive.expect_tx.shared.b64 _, [%0], %1;"
                         :: "r"(mb), "r"(2 * ROW_BYTES) : "memory");
            asm volatile("cp.async.bulk.shared::cluster.global.mbarrier::complete_tx::bytes "
                         "[%0], [%1], %2, [%3];"
                         :: "r"(smem_u32(smo)),
                            "l"(out + (size_t)row * Cc),
                            "r"(ROW_BYTES), "r"(mb) : "memory");
            asm volatile("cp.async.bulk.shared::cluster.global.mbarrier::complete_tx::bytes "
                         "[%0], [%1], %2, [%3];"
                         :: "r"(smem_u32(smt)),
                            "l"(d_Tt + (size_t)y * Cc),
                            "r"(ROW_BYTES), "r"(mb) : "memory");
        }
        // All lanes wait for both transfers (parity 0).
        {
            uint32_t done;
            asm volatile(
                "{\n\t.reg .pred p;\n\t"
                "mbarrier.try_wait.parity.acquire.cta.shared::cta.b64 p, [%1], 0;\n\t"
                "selp.b32 %0, 1, 0, p;\n\t}"
                : "=r"(done) : "r"(mb) : "memory");
            if (!done) {
                asm volatile(
                    "{\n\t.reg .pred P1;\n\t"
                    "WL_%=:\n\t"
                    "mbarrier.try_wait.parity.acquire.cta.shared::cta.b64 P1, [%0], 0, 0x989680;\n\t"
                    "@P1 bra.uni WD_%=;\n\t"
                    "bra.uni WL_%=;\n\t"
                    "WD_%=:\n\t}"
                    :: "r"(mb) : "memory");
            }
        }

        float s = 0.0f, dsum = 0.0f;
        #pragma unroll
        for (int i = 0; i < 8; i++) {
            int j = lane + 32 * i;
            if (j < C4) {
                float4 v = ((const float4*)smo)[j];
                float4 t = ((const float4*)smt)[j];
                float e0 = __expf(v.x), e1 = __expf(v.y);
                float e2 = __expf(v.z), e3 = __expf(v.w);
                s    += (e0 + e1) + (e2 + e3);
                dsum += (e0 * t.x + e1 * t.y) + (e2 * t.z + e3 * t.w);
            }
        }
        #pragma unroll
        for (int off = 16; off; off >>= 1) {
            s    += __shfl_xor_sync(0xffffffff, s,    off);
            dsum += __shfl_xor_sync(0xffffffff, dsum, off);
        }
        if (lane == 0) {
            float oy = smo[y];                  // target logit, already staged
            float beta = __expf(oy) / dsum;     // softmax denom cancels
            contrib = beta * (__logf(s) - oy);  // beta * (-log_softmax[y])
        }
    }

    if (lane == 0) part[warp] = contrib;
    __syncthreads();
    if (threadIdx.x == 0) {
        float t = 0.0f;
        #pragma unroll
        for (int w = 0; w < WPB; w++) t += part[w];
        atomicAdd(result, t);
    }
}

extern "C" void kernel_launch(void* const* d_in, const int* in_sizes, int n_in,
                              void* d_out, int out_size) {
    const float* out    = (const float*)d_in[0];
    const void*  target = d_in[1];
    const float* T      = (const float*)d_in[2];
    float* res = (float*)d_out;

    dim3 tb(32, 32);
    dim3 tg((Cc + 31) / 32, (Cc + 31) / 32);
    prep_kernel<<<tg, tb>>>(T, (const int*)target, res);

    reweight_kernel<<<NBLK, WPB * 32>>>(out, target, res);
}